// round 10
// baseline (speedup 1.0000x reference)
#include <cuda_runtime.h>
#include <cuda_fp16.h>
#include <cstdint>

#define B_   8192
#define IN_  2048
#define OUT_ 3072
#define S_   8

#define TM 128
#define TN 128
#define TK 64
#define NST (IN_ / TK)   // 32 K-stages
#define NBUF 3

// ---------------- scratch (device globals; no cudaMalloc allowed) -----------
__device__ int g_bucket[S_][B_];
__device__ int g_count[S_];

__device__ __half g_xf16[(size_t)B_ * IN_];
__device__ __half g_wf16[(size_t)S_ * IN_ * OUT_];   // [s][k][o]

// ---------------- helpers ----------------------------------------------------
__device__ __forceinline__ uint32_t smem_u32(const void* p) {
    uint32_t a;
    asm("{ .reg .u64 t; cvta.to.shared.u64 t, %1; cvt.u32.u64 %0, t; }"
        : "=r"(a) : "l"(p));
    return a;
}
__device__ __forceinline__ void cpasync16(uint32_t s, const void* g) {
    asm volatile("cp.async.cg.shared.global [%0], [%1], 16;"
                 :: "r"(s), "l"(g) : "memory");
}
#define CP_COMMIT() asm volatile("cp.async.commit_group;" ::: "memory")
#define CP_WAIT2()  asm volatile("cp.async.wait_group 2;"  ::: "memory")

#define LDSM_X4(r, a)                                                            \
    asm volatile("ldmatrix.sync.aligned.m8n8.x4.shared.b16 {%0,%1,%2,%3}, [%4];" \
                 : "=r"((r)[0]), "=r"((r)[1]), "=r"((r)[2]), "=r"((r)[3])        \
                 : "r"(a))
#define LDSM_X4_T(r, a)                                                          \
    asm volatile("ldmatrix.sync.aligned.m8n8.x4.trans.shared.b16 {%0,%1,%2,%3}, [%4];" \
                 : "=r"((r)[0]), "=r"((r)[1]), "=r"((r)[2]), "=r"((r)[3])        \
                 : "r"(a))

#define MMA16816(d, a, b0, b1)                                               \
    asm volatile("mma.sync.aligned.m16n8k16.row.col.f32.f16.f16.f32 "        \
                 "{%0,%1,%2,%3}, {%4,%5,%6,%7}, {%8,%9}, {%0,%1,%2,%3};"     \
                 : "+f"((d)[0]), "+f"((d)[1]), "+f"((d)[2]), "+f"((d)[3])    \
                 : "r"((a)[0]), "r"((a)[1]), "r"((a)[2]), "r"((a)[3]),       \
                   "r"(b0), "r"(b1))

// ---------------- fused prep: detect dtype + bucket rows by subject ----------
__global__ __launch_bounds__(1024)
void k_prep(const int* __restrict__ sid32) {
    __shared__ int s_cnt[S_];
    __shared__ int s_is64;
    const int tid = threadIdx.x;
    if (tid < S_) s_cnt[tid] = 0;
    if (tid == 0) s_is64 = 1;
    __syncthreads();
#pragma unroll
    for (int it = 0; it < B_ / 2 / 1024; it++) {
        int i = tid + it * 1024;
        if (sid32[2 * i + 1] != 0) s_is64 = 0;   // benign race, all write 0
    }
    __syncthreads();
    const int is64 = s_is64;
#pragma unroll
    for (int it = 0; it < B_ / 1024; it++) {
        int b = tid + it * 1024;
        int s = is64 ? sid32[2 * b] : sid32[b];
        int pos = atomicAdd(&s_cnt[s], 1);
        g_bucket[s][pos] = b;
    }
    __syncthreads();
    if (tid < S_) g_count[tid] = s_cnt[tid];
}

// ---------------- fused fp32 -> fp16 conversion ------------------------------
static constexpr size_t XU = (size_t)B_ * IN_ / 8;            // 8 floats / thread
static constexpr size_t WU = (size_t)S_ * IN_ * OUT_ / 8;

__device__ __forceinline__ uint4 conv8(const float4* src) {
    float4 v0 = src[0], v1 = src[1];
    __half2 a = __floats2half2_rn(v0.x, v0.y);
    __half2 b = __floats2half2_rn(v0.z, v0.w);
    __half2 c = __floats2half2_rn(v1.x, v1.y);
    __half2 d = __floats2half2_rn(v1.z, v1.w);
    uint4 r;
    r.x = *reinterpret_cast<uint32_t*>(&a);
    r.y = *reinterpret_cast<uint32_t*>(&b);
    r.z = *reinterpret_cast<uint32_t*>(&c);
    r.w = *reinterpret_cast<uint32_t*>(&d);
    return r;
}

__global__ void k_conv(const float* __restrict__ x, const float* __restrict__ w) {
    size_t i = (size_t)blockIdx.x * blockDim.x + threadIdx.x;
    if (i < XU) {
        ((uint4*)g_xf16)[i] = conv8((const float4*)x + i * 2);
    } else {
        size_t j = i - XU;
        if (j < WU)
            ((uint4*)g_wf16)[j] = conv8((const float4*)w + j * 2);
    }
}

// ---------------- GEMM -------------------------------------------------------
// smem per stage: A 128 rows x 128B (pad to 144B), B 64 rows x 256B (pad 272B).
// Both pads keep ldmatrix 8-row accesses on distinct banks.
static constexpr int STR_A  = 144;
static constexpr int STR_B  = 272;
static constexpr int OFF_A  = 0;
static constexpr int OFF_B  = 128 * STR_A;            // 18432
static constexpr int SSTAGE = OFF_B + TK * STR_B;     // 35840
static constexpr int SMEM_DYN = NBUF * SSTAGE;        // 107520

__global__ __launch_bounds__(128, 2)
void k_gemm(const float* __restrict__ bias, float* __restrict__ out) {
    const int s    = blockIdx.z;
    const int cnt  = g_count[s];
    const int row0 = blockIdx.y * TM;
    if (row0 >= cnt) return;
    const int col0 = blockIdx.x * TN;

    extern __shared__ char smem[];
    __shared__ int rowsm[TM];
    const uint32_t smb = smem_u32(smem);
    const int tid  = threadIdx.x;
    const int lane = tid & 31;
    const int wid  = tid >> 5;
    const int wm   = wid & 1;    // warp row (x64)
    const int wn   = wid >> 1;   // warp col (x64)

    {
        int r = row0 + tid;
        rowsm[tid] = (r < cnt) ? g_bucket[s][r] : -1;
    }
    __syncthreads();

    // cp.async addressing:
    //  A: one 128B row per thread (8 chunks of 16B)
    //  B: half a 256B row per thread (rowk = tid>>1, half = tid&1)
    int agrow = rowsm[tid];
    const size_t abase = (size_t)(agrow < 0 ? 0 : agrow) * IN_;
    const uint32_t asmem = tid * STR_A;

    const int brow  = tid >> 1;          // 0..63
    const int bhalf = (tid & 1) * 8;     // chunk offset 0 or 8
    const size_t bbase = (size_t)s * IN_ * OUT_ + (size_t)brow * OUT_ + col0 + bhalf * 8;
    const uint32_t bsmem = brow * STR_B + bhalf * 16;

    auto issue = [&](int st) {
        const int k0 = st * TK;
        const uint32_t sb = smb + (st % NBUF) * SSTAGE;
#pragma unroll
        for (int c = 0; c < 8; c++)
            cpasync16(sb + OFF_A + asmem + c * 16, g_xf16 + abase + k0 + c * 8);
#pragma unroll
        for (int c = 0; c < 8; c++)
            cpasync16(sb + OFF_B + bsmem + c * 16,
                      g_wf16 + bbase + (size_t)k0 * OUT_ + c * 8);
        CP_COMMIT();
    };

    issue(0);
    issue(1);
    issue(2);

    float acc[4][8][4];
#pragma unroll
    for (int i = 0; i < 4; i++)
#pragma unroll
        for (int j = 0; j < 8; j++)
#pragma unroll
            for (int k = 0; k < 4; k++) acc[i][j][k] = 0.f;

    const int a_row  = (lane & 15);
    const int a_coff = (lane >> 4) * 16;
    const int b_krow = (lane & 7) + ((lane >> 3) & 1) * 8;
    const int b_noff = (lane >> 4) * 8;

    uint32_t A[2][4][4], Bf[2][4][4];

    for (int st = 0; st < NST; st++) {
        CP_WAIT2();
        __syncthreads();
        const uint32_t sb = smb + (st % NBUF) * SSTAGE;

        // load kk=0 fragments into buffer 0
#pragma unroll
        for (int mi = 0; mi < 4; mi++) {
            uint32_t ad = sb + OFF_A +
                (wm * 64 + mi * 16 + a_row) * STR_A + a_coff;
            LDSM_X4(A[0][mi], ad);
        }
#pragma unroll
        for (int bj = 0; bj < 4; bj++) {
            uint32_t bd = sb + OFF_B + b_krow * STR_B +
                (wn * 64 + bj * 16 + b_noff) * 2;
            LDSM_X4_T(Bf[0][bj], bd);
        }

#pragma unroll
        for (int kk = 0; kk < 4; kk++) {
            const int pb = kk & 1;
            if (kk < 3) {
                const int nb = pb ^ 1;
#pragma unroll
                for (int mi = 0; mi < 4; mi++) {
                    uint32_t ad = sb + OFF_A +
                        (wm * 64 + mi * 16 + a_row) * STR_A +
                        (kk + 1) * 32 + a_coff;
                    LDSM_X4(A[nb][mi], ad);
                }
#pragma unroll
                for (int bj = 0; bj < 4; bj++) {
                    uint32_t bd = sb + OFF_B +
                        ((kk + 1) * 16 + b_krow) * STR_B +
                        (wn * 64 + bj * 16 + b_noff) * 2;
                    LDSM_X4_T(Bf[nb][bj], bd);
                }
            }
#pragma unroll
            for (int mi = 0; mi < 4; mi++)
#pragma unroll
                for (int nj = 0; nj < 8; nj++) {
                    const int g = nj >> 1, o = (nj & 1) * 2;
                    MMA16816(acc[mi][nj], A[pb][mi], Bf[pb][g][o], Bf[pb][g][o + 1]);
                }
        }
        __syncthreads();
        if (st + NBUF < NST) issue(st + NBUF);
        else CP_COMMIT();   // keep group accounting uniform
    }

    // ---- epilogue: D[m][n] + bias
#pragma unroll
    for (int nj = 0; nj < 8; nj++) {
        const int col = col0 + wn * 64 + nj * 8 + (lane & 3) * 2;
        const float2 bv = *(const float2*)(bias + s * OUT_ + col);
#pragma unroll
        for (int mi = 0; mi < 4; mi++) {
            const int mr = wm * 64 + mi * 16 + (lane >> 2);
            const int g0 = rowsm[mr];
            const int g1 = rowsm[mr + 8];
            if (g0 >= 0) {
                float2 v = make_float2(acc[mi][nj][0] + bv.x,
                                       acc[mi][nj][1] + bv.y);
                *(float2*)(out + (size_t)g0 * OUT_ + col) = v;
            }
            if (g1 >= 0) {
                float2 v = make_float2(acc[mi][nj][2] + bv.x,
                                       acc[mi][nj][3] + bv.y);
                *(float2*)(out + (size_t)g1 * OUT_ + col) = v;
            }
        }
    }
}

// ---------------- launch -----------------------------------------------------
extern "C" void kernel_launch(void* const* d_in, const int* in_sizes, int n_in,
                              void* d_out, int out_size) {
    const float* x    = (const float*)d_in[0];
    const int*   sid  = (const int*)d_in[1];
    const float* w    = (const float*)d_in[2];
    const float* bias = (const float*)d_in[3];
    float*       out  = (float*)d_out;

    k_prep<<<1, 1024>>>(sid);
    k_conv<<<(int)((XU + WU + 255) / 256), 256>>>(x, w);

    cudaFuncSetAttribute(k_gemm, cudaFuncAttributeMaxDynamicSharedMemorySize,
                         SMEM_DYN);
    dim3 grid(OUT_ / TN, B_ / TM, S_);
    k_gemm<<<grid, 128, SMEM_DYN>>>(bias, out);
}

// round 12
// speedup vs baseline: 1.6191x; 1.6191x over previous
#include <cuda_runtime.h>
#include <cuda_fp16.h>
#include <cstdint>

#define B_   8192
#define IN_  2048
#define OUT_ 3072
#define S_   8

#define TM 128
#define TN 128
#define TK 32
#define NST (IN_ / TK)   // 64 K-stages
#define NBUF 4

// ---------------- scratch (device globals; no cudaMalloc allowed) -----------
__device__ int g_bucket[S_][B_];
__device__ int g_count[S_];

__device__ __half g_xf16[(size_t)B_ * IN_];
__device__ __half g_wf16[(size_t)S_ * IN_ * OUT_];   // [s][k][o]

// ---------------- helpers ----------------------------------------------------
__device__ __forceinline__ uint32_t smem_u32(const void* p) {
    uint32_t a;
    asm("{ .reg .u64 t; cvta.to.shared.u64 t, %1; cvt.u32.u64 %0, t; }"
        : "=r"(a) : "l"(p));
    return a;
}
__device__ __forceinline__ void cpasync16(uint32_t s, const void* g) {
    asm volatile("cp.async.cg.shared.global [%0], [%1], 16;"
                 :: "r"(s), "l"(g) : "memory");
}
#define CP_COMMIT() asm volatile("cp.async.commit_group;" ::: "memory")
#define CP_WAIT3()  asm volatile("cp.async.wait_group 3;"  ::: "memory")

#define LDSM_X4(r, a)                                                            \
    asm volatile("ldmatrix.sync.aligned.m8n8.x4.shared.b16 {%0,%1,%2,%3}, [%4];" \
                 : "=r"((r)[0]), "=r"((r)[1]), "=r"((r)[2]), "=r"((r)[3])        \
                 : "r"(a))
#define LDSM_X4_T(r, a)                                                          \
    asm volatile("ldmatrix.sync.aligned.m8n8.x4.trans.shared.b16 {%0,%1,%2,%3}, [%4];" \
                 : "=r"((r)[0]), "=r"((r)[1]), "=r"((r)[2]), "=r"((r)[3])        \
                 : "r"(a))

#define MMA16816(d, a, b0, b1)                                               \
    asm volatile("mma.sync.aligned.m16n8k16.row.col.f32.f16.f16.f32 "        \
                 "{%0,%1,%2,%3}, {%4,%5,%6,%7}, {%8,%9}, {%0,%1,%2,%3};"     \
                 : "+f"((d)[0]), "+f"((d)[1]), "+f"((d)[2]), "+f"((d)[3])    \
                 : "r"((a)[0]), "r"((a)[1]), "r"((a)[2]), "r"((a)[3]),       \
                   "r"(b0), "r"(b1))

// ---------------- fused prep: detect dtype + bucket rows by subject ----------
__global__ __launch_bounds__(1024)
void k_prep(const int* __restrict__ sid32) {
    __shared__ int s_cnt[S_];
    __shared__ int s_is64;
    const int tid = threadIdx.x;
    if (tid < S_) s_cnt[tid] = 0;
    if (tid == 0) s_is64 = 1;
    __syncthreads();
#pragma unroll
    for (int it = 0; it < B_ / 2 / 1024; it++) {
        int i = tid + it * 1024;
        if (sid32[2 * i + 1] != 0) s_is64 = 0;   // benign race, all write 0
    }
    __syncthreads();
    const int is64 = s_is64;
#pragma unroll
    for (int it = 0; it < B_ / 1024; it++) {
        int b = tid + it * 1024;
        int s = is64 ? sid32[2 * b] : sid32[b];
        int pos = atomicAdd(&s_cnt[s], 1);
        g_bucket[s][pos] = b;
    }
    __syncthreads();
    if (tid < S_) g_count[tid] = s_cnt[tid];
}

// ---------------- fused fp32 -> fp16 conversion ------------------------------
static constexpr size_t XU = (size_t)B_ * IN_ / 8;            // 8 floats / thread
static constexpr size_t WU = (size_t)S_ * IN_ * OUT_ / 8;

__device__ __forceinline__ uint4 conv8(const float4* src) {
    float4 v0 = src[0], v1 = src[1];
    __half2 a = __floats2half2_rn(v0.x, v0.y);
    __half2 b = __floats2half2_rn(v0.z, v0.w);
    __half2 c = __floats2half2_rn(v1.x, v1.y);
    __half2 d = __floats2half2_rn(v1.z, v1.w);
    uint4 r;
    r.x = *reinterpret_cast<uint32_t*>(&a);
    r.y = *reinterpret_cast<uint32_t*>(&b);
    r.z = *reinterpret_cast<uint32_t*>(&c);
    r.w = *reinterpret_cast<uint32_t*>(&d);
    return r;
}

__global__ void k_conv(const float* __restrict__ x, const float* __restrict__ w) {
    size_t i = (size_t)blockIdx.x * blockDim.x + threadIdx.x;
    if (i < XU) {
        ((uint4*)g_xf16)[i] = conv8((const float4*)x + i * 2);
    } else {
        size_t j = i - XU;
        if (j < WU)
            ((uint4*)g_wf16)[j] = conv8((const float4*)w + j * 2);
    }
}

// ---------------- GEMM -------------------------------------------------------
// smem per stage: A 128 rows x 64B (pad to 80B), B 32 rows x 256B (pad 272B).
static constexpr int STR_A  = 80;
static constexpr int STR_B  = 272;
static constexpr int OFF_A  = 0;
static constexpr int OFF_B  = 128 * STR_A;            // 10240
static constexpr int SSTAGE = OFF_B + TK * STR_B;     // 18944
static constexpr int SMEM_DYN = NBUF * SSTAGE;        // 75776

__global__ __launch_bounds__(128)
void k_gemm(const float* __restrict__ bias, float* __restrict__ out) {
    const int s    = blockIdx.z;
    const int cnt  = g_count[s];
    const int row0 = blockIdx.y * TM;
    if (row0 >= cnt) return;
    const int col0 = blockIdx.x * TN;

    extern __shared__ char smem[];
    __shared__ int rowsm[TM];
    const uint32_t smb = smem_u32(smem);
    const int tid  = threadIdx.x;
    const int lane = tid & 31;
    const int wid  = tid >> 5;
    const int wm   = wid & 1;    // warp row (x64)
    const int wn   = wid >> 1;   // warp col (x64)

    if (tid < TM) {
        int r = row0 + tid;
        rowsm[tid] = (r < cnt) ? g_bucket[s][r] : -1;
    }
    __syncthreads();

    // cp.async addressing (coalesced): A 128 rows x 4 chunks of 16B
    // (4 consecutive threads cover one row's 64B); B 32 rows x 16 chunks
    // (16 consecutive threads cover one row's 256B).
    const int ar = tid >> 2, ac = tid & 3;
    size_t   aga[4];
    uint32_t asa[4];
#pragma unroll
    for (int l = 0; l < 4; l++) {
        int rr = ar + l * 32;
        int grow = rowsm[rr];
        if (grow < 0) grow = 0;
        aga[l] = (size_t)grow * IN_ + ac * 8;
        asa[l] = rr * STR_A + ac * 16;
    }
    const int bk = tid >> 4, bc = tid & 15;
    const size_t bgbase = (size_t)s * IN_ * OUT_ + col0 + bc * 8;
    uint32_t bsa[4];
#pragma unroll
    for (int l = 0; l < 4; l++) bsa[l] = (bk + l * 8) * STR_B + bc * 16;

    auto issue = [&](int st) {
        const int k0 = st * TK;
        const uint32_t sb = smb + (st % NBUF) * SSTAGE;
#pragma unroll
        for (int l = 0; l < 4; l++)
            cpasync16(sb + OFF_A + asa[l], g_xf16 + aga[l] + k0);
#pragma unroll
        for (int l = 0; l < 4; l++) {
            size_t g = bgbase + (size_t)(k0 + bk + l * 8) * OUT_;
            cpasync16(sb + OFF_B + bsa[l], g_wf16 + g);
        }
        CP_COMMIT();
    };

    issue(0);
    issue(1);
    issue(2);
    issue(3);

    float acc[4][8][4];
#pragma unroll
    for (int i = 0; i < 4; i++)
#pragma unroll
        for (int j = 0; j < 8; j++)
#pragma unroll
            for (int k = 0; k < 4; k++) acc[i][j][k] = 0.f;

    const int a_row  = (lane & 15);
    const int a_coff = (lane >> 4) * 16;
    const int b_krow = (lane & 7) + ((lane >> 3) & 1) * 8;
    const int b_noff = (lane >> 4) * 8;

    uint32_t A[2][4][4], Bf[2][4][4];

    for (int st = 0; st < NST; st++) {
        CP_WAIT3();
        __syncthreads();
        const uint32_t sb = smb + (st % NBUF) * SSTAGE;

        // load kk=0 fragments
#pragma unroll
        for (int mi = 0; mi < 4; mi++) {
            uint32_t ad = sb + OFF_A +
                (wm * 64 + mi * 16 + a_row) * STR_A + a_coff;
            LDSM_X4(A[0][mi], ad);
        }
#pragma unroll
        for (int bj = 0; bj < 4; bj++) {
            uint32_t bd = sb + OFF_B + b_krow * STR_B +
                (wn * 64 + bj * 16 + b_noff) * 2;
            LDSM_X4_T(Bf[0][bj], bd);
        }

#pragma unroll
        for (int kk = 0; kk < 2; kk++) {
            if (kk == 0) {
                // prefetch kk=1 fragments before issuing kk=0 MMAs
#pragma unroll
                for (int mi = 0; mi < 4; mi++) {
                    uint32_t ad = sb + OFF_A +
                        (wm * 64 + mi * 16 + a_row) * STR_A + 32 + a_coff;
                    LDSM_X4(A[1][mi], ad);
                }
#pragma unroll
                for (int bj = 0; bj < 4; bj++) {
                    uint32_t bd = sb + OFF_B + (16 + b_krow) * STR_B +
                        (wn * 64 + bj * 16 + b_noff) * 2;
                    LDSM_X4_T(Bf[1][bj], bd);
                }
            }
#pragma unroll
            for (int mi = 0; mi < 4; mi++)
#pragma unroll
                for (int nj = 0; nj < 8; nj++) {
                    const int g = nj >> 1, o = (nj & 1) * 2;
                    MMA16816(acc[mi][nj], A[kk][mi], Bf[kk][g][o], Bf[kk][g][o + 1]);
                }
        }
        __syncthreads();
        if (st + NBUF < NST) issue(st + NBUF);
        else CP_COMMIT();   // keep group accounting uniform
    }

    // ---- epilogue: D[m][n] + bias
#pragma unroll
    for (int nj = 0; nj < 8; nj++) {
        const int col = col0 + wn * 64 + nj * 8 + (lane & 3) * 2;
        const float2 bv = *(const float2*)(bias + s * OUT_ + col);
#pragma unroll
        for (int mi = 0; mi < 4; mi++) {
            const int mr = wm * 64 + mi * 16 + (lane >> 2);
            const int g0 = rowsm[mr];
            const int g1 = rowsm[mr + 8];
            if (g0 >= 0) {
                float2 v = make_float2(acc[mi][nj][0] + bv.x,
                                       acc[mi][nj][1] + bv.y);
                *(float2*)(out + (size_t)g0 * OUT_ + col) = v;
            }
            if (g1 >= 0) {
                float2 v = make_float2(acc[mi][nj][2] + bv.x,
                                       acc[mi][nj][3] + bv.y);
                *(float2*)(out + (size_t)g1 * OUT_ + col) = v;
            }
        }
    }
}

// ---------------- launch -----------------------------------------------------
extern "C" void kernel_launch(void* const* d_in, const int* in_sizes, int n_in,
                              void* d_out, int out_size) {
    const float* x    = (const float*)d_in[0];
    const int*   sid  = (const int*)d_in[1];
    const float* w    = (const float*)d_in[2];
    const float* bias = (const float*)d_in[3];
    float*       out  = (float*)d_out;

    k_prep<<<1, 1024>>>(sid);
    k_conv<<<(int)((XU + WU + 255) / 256), 256>>>(x, w);

    cudaFuncSetAttribute(k_gemm, cudaFuncAttributeMaxDynamicSharedMemorySize,
                         SMEM_DYN);
    dim3 grid(OUT_ / TN, B_ / TM, S_);
    k_gemm<<<grid, 128, SMEM_DYN>>>(bias, out);
}

// round 14
// speedup vs baseline: 1.6208x; 1.0011x over previous
#include <cuda_runtime.h>
#include <cuda_fp16.h>
#include <cstdint>

#define B_   8192
#define IN_  2048
#define OUT_ 3072
#define S_   8

#define TM 128
#define TN 128
#define TK 32
#define NST (IN_ / TK)   // 64 K-stages
#define NBUF 4

// ---------------- scratch (device globals; no cudaMalloc allowed) -----------
__device__ int g_bucket[S_][B_];
__device__ int g_count[S_];

__device__ __half g_xf16[(size_t)B_ * IN_];
__device__ __half g_wf16[(size_t)S_ * IN_ * OUT_];   // [s][k][o]

// ---------------- helpers ----------------------------------------------------
__device__ __forceinline__ uint32_t smem_u32(const void* p) {
    uint32_t a;
    asm("{ .reg .u64 t; cvta.to.shared.u64 t, %1; cvt.u32.u64 %0, t; }"
        : "=r"(a) : "l"(p));
    return a;
}
__device__ __forceinline__ void cpasync16(uint32_t s, const void* g) {
    asm volatile("cp.async.cg.shared.global [%0], [%1], 16;"
                 :: "r"(s), "l"(g) : "memory");
}
#define CP_COMMIT() asm volatile("cp.async.commit_group;" ::: "memory")
#define CP_WAIT3()  asm volatile("cp.async.wait_group 3;"  ::: "memory")

#define LDSM_X4(r, a)                                                            \
    asm volatile("ldmatrix.sync.aligned.m8n8.x4.shared.b16 {%0,%1,%2,%3}, [%4];" \
                 : "=r"((r)[0]), "=r"((r)[1]), "=r"((r)[2]), "=r"((r)[3])        \
                 : "r"(a))
#define LDSM_X4_T(r, a)                                                          \
    asm volatile("ldmatrix.sync.aligned.m8n8.x4.trans.shared.b16 {%0,%1,%2,%3}, [%4];" \
                 : "=r"((r)[0]), "=r"((r)[1]), "=r"((r)[2]), "=r"((r)[3])        \
                 : "r"(a))

#define MMA16816(d, a, b0, b1)                                               \
    asm volatile("mma.sync.aligned.m16n8k16.row.col.f32.f16.f16.f32 "        \
                 "{%0,%1,%2,%3}, {%4,%5,%6,%7}, {%8,%9}, {%0,%1,%2,%3};"     \
                 : "+f"((d)[0]), "+f"((d)[1]), "+f"((d)[2]), "+f"((d)[3])    \
                 : "r"((a)[0]), "r"((a)[1]), "r"((a)[2]), "r"((a)[3]),       \
                   "r"(b0), "r"(b1))

// ---------------- fused prep: detect dtype + bucket rows by subject ----------
__global__ __launch_bounds__(1024)
void k_prep(const int* __restrict__ sid32) {
    __shared__ int s_cnt[S_];
    __shared__ int s_is64;
    const int tid = threadIdx.x;
    if (tid < S_) s_cnt[tid] = 0;
    if (tid == 0) s_is64 = 1;
    __syncthreads();
#pragma unroll
    for (int it = 0; it < B_ / 2 / 1024; it++) {
        int i = tid + it * 1024;
        if (sid32[2 * i + 1] != 0) s_is64 = 0;   // benign race, all write 0
    }
    __syncthreads();
    const int is64 = s_is64;
#pragma unroll
    for (int it = 0; it < B_ / 1024; it++) {
        int b = tid + it * 1024;
        int s = is64 ? sid32[2 * b] : sid32[b];
        int pos = atomicAdd(&s_cnt[s], 1);
        g_bucket[s][pos] = b;
    }
    __syncthreads();
    if (tid < S_) g_count[tid] = s_cnt[tid];
}

// ---------------- fused fp32 -> fp16 conversion ------------------------------
static constexpr size_t XU = (size_t)B_ * IN_ / 8;            // 8 floats / thread
static constexpr size_t WU = (size_t)S_ * IN_ * OUT_ / 8;

__device__ __forceinline__ uint4 conv8(const float4* src) {
    float4 v0 = src[0], v1 = src[1];
    __half2 a = __floats2half2_rn(v0.x, v0.y);
    __half2 b = __floats2half2_rn(v0.z, v0.w);
    __half2 c = __floats2half2_rn(v1.x, v1.y);
    __half2 d = __floats2half2_rn(v1.z, v1.w);
    uint4 r;
    r.x = *reinterpret_cast<uint32_t*>(&a);
    r.y = *reinterpret_cast<uint32_t*>(&b);
    r.z = *reinterpret_cast<uint32_t*>(&c);
    r.w = *reinterpret_cast<uint32_t*>(&d);
    return r;
}

__global__ void k_conv(const float* __restrict__ x, const float* __restrict__ w) {
    size_t i = (size_t)blockIdx.x * blockDim.x + threadIdx.x;
    if (i < XU) {
        ((uint4*)g_xf16)[i] = conv8((const float4*)x + i * 2);
    } else {
        size_t j = i - XU;
        if (j < WU)
            ((uint4*)g_wf16)[j] = conv8((const float4*)w + j * 2);
    }
}

// ---------------- GEMM -------------------------------------------------------
// 256 threads, 8 warps of 64x32 (2 warp-rows x 4 warp-cols).
// smem per stage: A 128 rows x 64B (pad to 80B), B 32 rows x 256B (pad 272B).
static constexpr int STR_A  = 80;
static constexpr int STR_B  = 272;
static constexpr int OFF_A  = 0;
static constexpr int OFF_B  = 128 * STR_A;            // 10240
static constexpr int SSTAGE = OFF_B + TK * STR_B;     // 18944
static constexpr int SMEM_DYN = NBUF * SSTAGE;        // 75776

__global__ __launch_bounds__(256, 2)
void k_gemm(const float* __restrict__ bias, float* __restrict__ out) {
    const int s    = blockIdx.z;
    const int cnt  = g_count[s];
    const int row0 = blockIdx.y * TM;
    if (row0 >= cnt) return;
    const int col0 = blockIdx.x * TN;

    extern __shared__ char smem[];
    __shared__ int rowsm[TM];
    const uint32_t smb = smem_u32(smem);
    const int tid  = threadIdx.x;
    const int lane = tid & 31;
    const int wid  = tid >> 5;
    const int wm   = wid & 1;    // warp row (x64)
    const int wn   = wid >> 1;   // warp col (x32)

    if (tid < TM) {
        int r = row0 + tid;
        rowsm[tid] = (r < cnt) ? g_bucket[s][r] : -1;
    }
    __syncthreads();

    // cp.async addressing (coalesced):
    //  A: 128 rows x 4 chunks of 16B; 256 threads -> 2 rows-groups each
    //  B: 32 rows x 16 chunks of 16B; 256 threads -> 2 rows-groups each
    const int ar = tid >> 2, ac = tid & 3;          // ar 0..63
    size_t   aga[2];
    uint32_t asa[2];
#pragma unroll
    for (int l = 0; l < 2; l++) {
        int rr = ar + l * 64;
        int grow = rowsm[rr];
        if (grow < 0) grow = 0;
        aga[l] = (size_t)grow * IN_ + ac * 8;
        asa[l] = rr * STR_A + ac * 16;
    }
    const int bk = tid >> 4, bc = tid & 15;         // bk 0..15
    const size_t bgbase = (size_t)s * IN_ * OUT_ + col0 + bc * 8;
    uint32_t bsa[2];
#pragma unroll
    for (int l = 0; l < 2; l++) bsa[l] = (bk + l * 16) * STR_B + bc * 16;

    auto issue = [&](int st) {
        const int k0 = st * TK;
        const uint32_t sb = smb + (st % NBUF) * SSTAGE;
#pragma unroll
        for (int l = 0; l < 2; l++)
            cpasync16(sb + OFF_A + asa[l], g_xf16 + aga[l] + k0);
#pragma unroll
        for (int l = 0; l < 2; l++) {
            size_t g = bgbase + (size_t)(k0 + bk + l * 16) * OUT_;
            cpasync16(sb + OFF_B + bsa[l], g_wf16 + g);
        }
        CP_COMMIT();
    };

    issue(0);
    issue(1);
    issue(2);
    issue(3);

    float acc[4][4][4];
#pragma unroll
    for (int i = 0; i < 4; i++)
#pragma unroll
        for (int j = 0; j < 4; j++)
#pragma unroll
            for (int k = 0; k < 4; k++) acc[i][j][k] = 0.f;

    const int a_row  = (lane & 15);
    const int a_coff = (lane >> 4) * 16;
    const int b_krow = (lane & 7) + ((lane >> 3) & 1) * 8;
    const int b_noff = (lane >> 4) * 8;

    for (int st = 0; st < NST; st++) {
        CP_WAIT3();
        __syncthreads();
        const uint32_t sb = smb + (st % NBUF) * SSTAGE;

#pragma unroll
        for (int kk = 0; kk < 2; kk++) {
            uint32_t A[4][4], Bf[2][4];
#pragma unroll
            for (int mi = 0; mi < 4; mi++) {
                uint32_t ad = sb + OFF_A +
                    (wm * 64 + mi * 16 + a_row) * STR_A + kk * 32 + a_coff;
                LDSM_X4(A[mi], ad);
            }
#pragma unroll
            for (int bj = 0; bj < 2; bj++) {
                uint32_t bd = sb + OFF_B +
                    (kk * 16 + b_krow) * STR_B +
                    (wn * 32 + bj * 16 + b_noff) * 2;
                LDSM_X4_T(Bf[bj], bd);
            }
#pragma unroll
            for (int mi = 0; mi < 4; mi++)
#pragma unroll
                for (int nj = 0; nj < 4; nj++) {
                    const int g = nj >> 1, o = (nj & 1) * 2;
                    MMA16816(acc[mi][nj], A[mi], Bf[g][o], Bf[g][o + 1]);
                }
        }
        __syncthreads();
        if (st + NBUF < NST) issue(st + NBUF);
        else CP_COMMIT();   // keep group accounting uniform
    }

    // ---- epilogue: D[m][n] + bias
#pragma unroll
    for (int nj = 0; nj < 4; nj++) {
        const int col = col0 + wn * 32 + nj * 8 + (lane & 3) * 2;
        const float2 bv = *(const float2*)(bias + s * OUT_ + col);
#pragma unroll
        for (int mi = 0; mi < 4; mi++) {
            const int mr = wm * 64 + mi * 16 + (lane >> 2);
            const int g0 = rowsm[mr];
            const int g1 = rowsm[mr + 8];
            if (g0 >= 0) {
                float2 v = make_float2(acc[mi][nj][0] + bv.x,
                                       acc[mi][nj][1] + bv.y);
                *(float2*)(out + (size_t)g0 * OUT_ + col) = v;
            }
            if (g1 >= 0) {
                float2 v = make_float2(acc[mi][nj][2] + bv.x,
                                       acc[mi][nj][3] + bv.y);
                *(float2*)(out + (size_t)g1 * OUT_ + col) = v;
            }
        }
    }
}

// ---------------- launch -----------------------------------------------------
extern "C" void kernel_launch(void* const* d_in, const int* in_sizes, int n_in,
                              void* d_out, int out_size) {
    const float* x    = (const float*)d_in[0];
    const int*   sid  = (const int*)d_in[1];
    const float* w    = (const float*)d_in[2];
    const float* bias = (const float*)d_in[3];
    float*       out  = (float*)d_out;

    k_prep<<<1, 1024>>>(sid);
    k_conv<<<(int)((XU + WU + 255) / 256), 256>>>(x, w);

    cudaFuncSetAttribute(k_gemm, cudaFuncAttributeMaxDynamicSharedMemorySize,
                         SMEM_DYN);
    dim3 grid(OUT_ / TN, B_ / TM, S_);
    k_gemm<<<grid, 256, SMEM_DYN>>>(bias, out);
}